// round 7
// baseline (speedup 1.0000x reference)
#include <cuda_runtime.h>
#include <cuda_bf16.h>

#define NT 48
#define SEQ 512
#define BATCH 1024
#define BPB 2                     // batches per block
#define HALF 24                   // i-elements per thread
#define THREADS (BPB * NT * 2)    // 192 threads = 6 warps

// Viterbi forward, i-dim split 2-way per (b,j), fused (value,index) max-tree.
//   thread r = j*2 + h within a 96-thread batch group (partners = adjacent lanes)
//   - T[ibase..ibase+23][j] cached in 24 registers
//   - state in SMEM, double buffered, one barrier per step
//   - argmax carried as float index through the tree: FMNMX + FSETP.GT + FSEL
//     per node (all 4-cyc ops, no predicated-guard chains)
//   - partner merge via 2x shfl_xor(1); exact first-occurrence tie-break
__global__ __launch_bounds__(THREADS, 4)
void crf_viterbi_kernel(const float* __restrict__ pot,
                        const float* __restrict__ trans,
                        float* __restrict__ out)
{
    __shared__ __align__(16) float st[2][BPB][NT];

    const int tid = threadIdx.x;
    const int grp = tid / (2 * NT);      // local batch 0/1
    const int r   = tid - grp * 2 * NT;
    const int j   = r >> 1;              // tag column
    const int h   = r & 1;               // i-range half
    const int b   = blockIdx.x * BPB + grp;
    const int ibase = h * HALF;
    const float ibase_f = (float)ibase;

    // This thread's half of transition column T[i][j]
    float tc[HALF];
#pragma unroll
    for (int k = 0; k < HALF; k++) tc[k] = trans[(ibase + k) * NT + j];

    const float* potb = pot + (size_t)b * SEQ * NT + j;
    float* bpp        = out + (size_t)b * (SEQ - 1) * NT + j;
    float* scores     = out + (size_t)BATCH * (SEQ - 1) * NT;

    float ns = potb[0];
    if (h == 0) st[0][grp][j] = ns;
    __syncthreads();

    // 2-deep prefetch of unary potentials (same address for both partners)
    const float* pp = potb + 3 * NT;
    float pn1 = potb[NT];
    float pn2 = potb[2 * NT];
    int buf = 0;

    for (int t = 1; t < SEQ; ++t) {
        const float p = pn1;
        pn1 = pn2;
        if (t + 2 < SEQ) { pn2 = *pp; pp += NT; }

        // Load this thread's 24 state values (6x LDS.128) and add tc
        float v[HALF];
        const float4* sp = (const float4*)(&st[buf][grp][ibase]);
#pragma unroll
        for (int k = 0; k < HALF / 4; k++) {
            float4 q = sp[k];
            v[4 * k + 0] = q.x + tc[4 * k + 0];
            v[4 * k + 1] = q.y + tc[4 * k + 1];
            v[4 * k + 2] = q.z + tc[4 * k + 2];
            v[4 * k + 3] = q.w + tc[4 * k + 3];
        }

        // Fused (value, float-index) balanced tree, local indices 0..23.
        // Strict r>l per node => leftmost (lowest index) wins on ties.
        float fi[HALF];
#pragma unroll
        for (int k = 0; k < HALF; k++) fi[k] = (float)k;

#pragma unroll
        for (int n = HALF; n > 3; n >>= 1) {
#pragma unroll
            for (int k = 0; k < n / 2; k++) {
                const float lv = v[2 * k],  rv = v[2 * k + 1];
                const float li = fi[2 * k], ri = fi[2 * k + 1];
                const bool  pr = (rv > lv);
                v[k]  = fmaxf(lv, rv);
                fi[k] = pr ? ri : li;
            }
        }
        // 3 -> 1 (keep index order: (0,1) then vs 2)
        {
            const bool p01 = (v[1] > v[0]);
            float mv = fmaxf(v[0], v[1]);
            float mi = p01 ? fi[1] : fi[0];
            const bool p2 = (v[2] > mv);
            v[0]  = fmaxf(mv, v[2]);
            fi[0] = p2 ? fi[2] : mi;
        }
        float m    = v[0];
        float fidx = fi[0] + ibase_f;     // globalize index

        // Partner merge (adjacent lane). Tie -> lower index (exact argmax).
        const float mo = __shfl_xor_sync(0xffffffffu, m, 1);
        const float io = __shfl_xor_sync(0xffffffffu, fidx, 1);
        if (mo > m || (mo == m && io < fidx)) { m = mo; fidx = io; }

        ns = p + m;                            // bit-exact vs reference
        if (h == 0) st[buf ^ 1][grp][j] = ns;  // publish new state
        else        bpp[0] = fidx;             // publish backpointer
        bpp += NT;
        __syncthreads();
        buf ^= 1;
    }

    if (h == 0) scores[(size_t)b * NT + j] = ns;
}

extern "C" void kernel_launch(void* const* d_in, const int* in_sizes, int n_in,
                              void* d_out, int out_size)
{
    const float* pot   = (const float*)d_in[0];
    const float* trans = (const float*)d_in[1];
    float* out         = (float*)d_out;
    crf_viterbi_kernel<<<BATCH / BPB, THREADS>>>(pot, trans, out);
}

// round 8
// speedup vs baseline: 1.1582x; 1.1582x over previous
#include <cuda_runtime.h>
#include <cuda_bf16.h>

#define NT 48
#define SEQ 512
#define BATCH 1024
#define BPB 2                 // batches per block
#define THREADS (BPB * NT)    // 96 threads = 3 warps

// Viterbi forward: one thread per (batch, tag_j).
//   - T[:, j] column in 48 registers
//   - state in SMEM, double buffered, one barrier per step
//   - fused (value, float-index) balanced tree: FSETP + FSEL + FMNMX per node
//     (FSEL rides the fma pipe, FMNMX/FSETP the alu pipe -> ~1:1 pipe balance)
//   - strict r>l per node, left = lower index => exact first-occurrence argmax
__global__ __launch_bounds__(THREADS, 4)
void crf_viterbi_kernel(const float* __restrict__ pot,
                        const float* __restrict__ trans,
                        float* __restrict__ out)
{
    __shared__ __align__(16) float st[2][BPB][NT];

    const int tid = threadIdx.x;
    const int lb  = tid / NT;
    const int j   = tid - lb * NT;
    const int b   = blockIdx.x * BPB + lb;

    // Transition column T[i][j] in registers
    float tc[NT];
#pragma unroll
    for (int i = 0; i < NT; i++) tc[i] = trans[i * NT + j];

    const float* potb = pot + (size_t)b * SEQ * NT + j;
    float* bpp        = out + (size_t)b * (SEQ - 1) * NT + j;
    float* scores     = out + (size_t)BATCH * (SEQ - 1) * NT;

    float ns = potb[0];
    st[0][lb][j] = ns;
    __syncthreads();

    // 2-deep prefetch of unary potentials, running pointer
    const float* pp = potb + 3 * NT;
    float pn1 = potb[NT];
    float pn2 = potb[2 * NT];
    int buf = 0;

#pragma unroll 2
    for (int t = 1; t < SEQ; ++t) {
        const float p = pn1;
        pn1 = pn2;
        if (t + 2 < SEQ) { pn2 = *pp; pp += NT; }

        // Load state (12x LDS.128, broadcast within batch group) and add tc
        float s[NT];
        const float4* sp = (const float4*)st[buf][lb];
#pragma unroll
        for (int k = 0; k < NT / 4; k++) {
            float4 q = sp[k];
            s[4 * k + 0] = q.x + tc[4 * k + 0];
            s[4 * k + 1] = q.y + tc[4 * k + 1];
            s[4 * k + 2] = q.z + tc[4 * k + 2];
            s[4 * k + 3] = q.w + tc[4 * k + 3];
        }

        // Fused (value, float-index) tree. 48 -> 24 -> 12 -> 6 -> 3 -> 1.
        // Node: pr = (rv > lv); v = fmaxf(lv, rv); fi = pr ? ri : li.
        // Tie -> left (lower index) survives: exact jnp.argmax semantics.
        float v1[24], i1[24];
#pragma unroll
        for (int k = 0; k < 24; k++) {
            const bool pr = (s[2 * k + 1] > s[2 * k]);
            v1[k] = fmaxf(s[2 * k], s[2 * k + 1]);
            i1[k] = pr ? (float)(2 * k + 1) : (float)(2 * k);
        }
        float v2[12], i2[12];
#pragma unroll
        for (int k = 0; k < 12; k++) {
            const bool pr = (v1[2 * k + 1] > v1[2 * k]);
            v2[k] = fmaxf(v1[2 * k], v1[2 * k + 1]);
            i2[k] = pr ? i1[2 * k + 1] : i1[2 * k];
        }
        float v3[6], i3[6];
#pragma unroll
        for (int k = 0; k < 6; k++) {
            const bool pr = (v2[2 * k + 1] > v2[2 * k]);
            v3[k] = fmaxf(v2[2 * k], v2[2 * k + 1]);
            i3[k] = pr ? i2[2 * k + 1] : i2[2 * k];
        }
        float v4[3], i4[3];
#pragma unroll
        for (int k = 0; k < 3; k++) {
            const bool pr = (v3[2 * k + 1] > v3[2 * k]);
            v4[k] = fmaxf(v3[2 * k], v3[2 * k + 1]);
            i4[k] = pr ? i3[2 * k + 1] : i3[2 * k];
        }
        // Ordered 3 -> 1: (0,1) first, then vs 2 (higher indices on the right)
        const bool p01 = (v4[1] > v4[0]);
        const float mv01 = fmaxf(v4[0], v4[1]);
        const float mi01 = p01 ? i4[1] : i4[0];
        const bool p2  = (v4[2] > mv01);
        const float m    = fmaxf(mv01, v4[2]);
        const float fidx = p2 ? i4[2] : mi01;

        ns = p + m;                        // bit-exact vs reference
        st[buf ^ 1][lb][j] = ns;
        bpp[0] = fidx;
        bpp += NT;
        __syncthreads();
        buf ^= 1;
    }

    scores[(size_t)b * NT + j] = ns;
}

extern "C" void kernel_launch(void* const* d_in, const int* in_sizes, int n_in,
                              void* d_out, int out_size)
{
    const float* pot   = (const float*)d_in[0];
    const float* trans = (const float*)d_in[1];
    float* out         = (float*)d_out;
    crf_viterbi_kernel<<<BATCH / BPB, THREADS>>>(pot, trans, out);
}